// round 9
// baseline (speedup 1.0000x reference)
#include <cuda_runtime.h>
#include <cuda_bf16.h>
#include <mma.h>
#include <math.h>
#include <stdint.h>

#define DIM      128
#define HEADS    8
#define DH       16
#define FFD      512
#define DEPTH    4
#define EPSV     1e-5f
#define NTHREADS 512
#define NWARPS   16
#define DPAD     132     // fp32 row stride (h, D scratch)
#define APAD     136     // bf16 row stride for A (LN / attn-out) arrays
#define TPAD     264     // bf16 row stride for FF-half intermediate
#define KPAD     66      // fp32 token stride for kT/vT

// Split weights, natural [K][128] planes: hi plane then lo plane per block.
// Per stack-layer: Wq,Wk,Wv,Wo (2*128*128 each) + W1 j0..3 (2*128*128 each)
// + W2 (2*512*128) = 393216 bf16. 8 stack-layers total.
__device__ __nv_bfloat16 g_wsplit[8 * 393216];

// Intermediate between channel stack and temporal stack
__device__ float g_mid[64 * 64 * DIM];

struct StackParams {
    const float *Wq, *Wk, *Wv, *Wo, *bo;
    const float *g1, *be1, *g2, *be2;
    const float *W1, *bf1, *W2, *bf2;
};

__device__ __forceinline__ float gelu_tanh(float x) {
    float x3 = x * x * x;
    return 0.5f * x * (1.0f + tanhf(0.7978845608028654f * (x + 0.044715f * x3)));
}

// pack (a,b) -> hi word (bf16(a) low half, bf16(b) high half) + lo word (residuals)
__device__ __forceinline__ void split2(float a, float b, uint32_t& hi, uint32_t& lo) {
    __nv_bfloat16 ah = __float2bfloat16_rn(a);
    __nv_bfloat16 bh = __float2bfloat16_rn(b);
    __nv_bfloat16 al = __float2bfloat16_rn(a - __bfloat162float(ah));
    __nv_bfloat16 bl = __float2bfloat16_rn(b - __bfloat162float(bh));
    hi = ((uint32_t)__bfloat16_as_ushort(bh) << 16) | (uint32_t)__bfloat16_as_ushort(ah);
    lo = ((uint32_t)__bfloat16_as_ushort(bl) << 16) | (uint32_t)__bfloat16_as_ushort(al);
}

// ---------------- cp.async helpers ----------------
__device__ __forceinline__ void cp16(void* dst, const void* src) {
    uint32_t d = (uint32_t)__cvta_generic_to_shared(dst);
    asm volatile("cp.async.ca.shared.global [%0], [%1], 16;" :: "r"(d), "l"(src));
}
__device__ __forceinline__ void cp_commit() { asm volatile("cp.async.commit_group;"); }
__device__ __forceinline__ void cp_wait0()  { asm volatile("cp.async.wait_group 0;"); }

// Stage one weight slab (16 k-rows x 128 cols, hi plane then lo plane) to smem.
// gW = block base (hi plane); lo plane at gW + loOfs. 512 threads * 16B = 8KB.
__device__ __forceinline__ void stage_slab(__nv_bfloat16* dst, const __nv_bfloat16* gW,
                                           int slab, int loOfs, int tid)
{
    const __nv_bfloat16* src = (tid < 256)
        ? gW + (size_t)slab * 2048 + tid * 8
        : gW + loOfs + (size_t)slab * 2048 + (tid - 256) * 8;
    cp16(dst + tid * 8, src);
}

// ---------------------------------------------------------------------------
// wmma GEMM: D[64 x 128] = A @ W with K = 16*KSLABS.
// A = hi/lo bf16 arrays, row-major, leading dim lda (tokens x K).
// W streamed from g_wsplit (natural [K][128] planes) via cp.async dbl buffer.
// 16 warps: row strip = wy&3 (16 tokens), col group = wy>>2 (32 cols).
// 3-term split: D = Ah*Wh + Ah*Wl + Al*Wh (fp32 accum). Result -> D scratch.
// Ends with __syncthreads().
// ---------------------------------------------------------------------------
template<int KSLABS>
__device__ __forceinline__ void gemm_wmma(
    const __nv_bfloat16* __restrict__ Ah, const __nv_bfloat16* __restrict__ Al, int lda,
    const __nv_bfloat16* __restrict__ gW, int loOfs,
    float* __restrict__ D, __nv_bfloat16* __restrict__ wsm, int tid)
{
    using namespace nvcuda::wmma;
    const int wy   = tid >> 5;
    const int mrow = wy & 3;
    const int ngrp = wy >> 2;

    fragment<accumulator, 16, 16, 16, float> c0, c1;
    fill_fragment(c0, 0.f);
    fill_fragment(c1, 0.f);

    stage_slab(wsm, gW, 0, loOfs, tid);
    cp_commit();

    for (int s = 0; s < KSLABS; s++) {
        cp_wait0();
        __syncthreads();
        if (s + 1 < KSLABS) {
            stage_slab(wsm + ((s + 1) & 1) * 4096, gW, s + 1, loOfs, tid);
            cp_commit();
        }
        const __nv_bfloat16* ws = wsm + (s & 1) * 4096;

        fragment<matrix_a, 16, 16, 16, __nv_bfloat16, row_major> ah, al;
        load_matrix_sync(ah, Ah + (size_t)(mrow * 16) * lda + s * 16, lda);
        load_matrix_sync(al, Al + (size_t)(mrow * 16) * lda + s * 16, lda);

        fragment<matrix_b, 16, 16, 16, __nv_bfloat16, row_major> bh, bl;
        load_matrix_sync(bh, ws + ngrp * 32, 128);
        load_matrix_sync(bl, ws + 2048 + ngrp * 32, 128);
        mma_sync(c0, ah, bh, c0);
        mma_sync(c0, ah, bl, c0);
        mma_sync(c0, al, bh, c0);

        load_matrix_sync(bh, ws + ngrp * 32 + 16, 128);
        load_matrix_sync(bl, ws + 2048 + ngrp * 32 + 16, 128);
        mma_sync(c1, ah, bh, c1);
        mma_sync(c1, ah, bl, c1);
        mma_sync(c1, al, bh, c1);
    }

    store_matrix_sync(D + (size_t)(mrow * 16) * DPAD + ngrp * 32,      c0, DPAD, mem_row_major);
    store_matrix_sync(D + (size_t)(mrow * 16) * DPAD + ngrp * 32 + 16, c1, DPAD, mem_row_major);
    __syncthreads();
}

// ---------------------------------------------------------------------------
// LayerNorm: reads h [N][DPAD] fp32, writes bf16 hi/lo arrays [N][APAD].
template<int N>
__device__ __forceinline__ void layernorm_split(
    const float* __restrict__ src, __nv_bfloat16* __restrict__ Ahb,
    __nv_bfloat16* __restrict__ Alb,
    const float* __restrict__ g, const float* __restrict__ b, int tid)
{
    int lane = tid & 31, wid = tid >> 5;
    float4 g4 = *(const float4*)(g + lane * 4);
    float4 b4 = *(const float4*)(b + lane * 4);
    for (int c = wid; c < N; c += NWARPS) {
        float4 x = *(const float4*)(src + c * DPAD + lane * 4);
        float s = x.x + x.y + x.z + x.w;
#pragma unroll
        for (int o = 16; o; o >>= 1) s += __shfl_xor_sync(0xffffffffu, s, o);
        float m = s * (1.0f / DIM);
        float dx = x.x - m, dy = x.y - m, dz = x.z - m, dw = x.w - m;
        float v = dx * dx + dy * dy + dz * dz + dw * dw;
#pragma unroll
        for (int o = 16; o; o >>= 1) v += __shfl_xor_sync(0xffffffffu, v, o);
        float rs = rsqrtf(v * (1.0f / DIM) + EPSV);
        float v0 = dx * rs * g4.x + b4.x;
        float v1 = dy * rs * g4.y + b4.y;
        float v2 = dz * rs * g4.z + b4.z;
        float v3 = dw * rs * g4.w + b4.w;
        uint32_t h0, l0, h1, l1;
        split2(v0, v1, h0, l0);
        split2(v2, v3, h1, l1);
        uint32_t* oh = (uint32_t*)(Ahb + (size_t)c * APAD);
        uint32_t* ol = (uint32_t*)(Alb + (size_t)c * APAD);
        oh[lane * 2]     = h0;
        oh[lane * 2 + 1] = h1;
        ol[lane * 2]     = l0;
        ol[lane * 2 + 1] = l1;
    }
}

// softmax over the 16-feature head dim on Q (= D scratch, stride DPAD)
template<int N>
__device__ __forceinline__ void softmax_feat(float* __restrict__ q, int tid)
{
    int lane = tid & 31, wid = tid >> 5;
    for (int c = wid; c < N; c += NWARPS) {
        float4 x = *(const float4*)(q + c * DPAD + lane * 4);
        float m = fmaxf(fmaxf(x.x, x.y), fmaxf(x.z, x.w));
        m = fmaxf(m, __shfl_xor_sync(0xffffffffu, m, 1));
        m = fmaxf(m, __shfl_xor_sync(0xffffffffu, m, 2));
        float4 e;
        e.x = expf(x.x - m); e.y = expf(x.y - m);
        e.z = expf(x.z - m); e.w = expf(x.w - m);
        float s = e.x + e.y + e.z + e.w;
        s += __shfl_xor_sync(0xffffffffu, s, 1);
        s += __shfl_xor_sync(0xffffffffu, s, 2);
        float sc = 0.25f / s;
        e.x *= sc; e.y *= sc; e.z *= sc; e.w *= sc;
        *(float4*)(q + c * DPAD + lane * 4) = e;
    }
}

// softmax over the sequence dim on kT [128][KPAD]
template<int N>
__device__ __forceinline__ void softmax_seq_T(float* __restrict__ kT, int tid)
{
    if (tid < DIM) {
        float* p = kT + tid * KPAD;
        float m = -1e30f;
        for (int c = 0; c < N; c++) m = fmaxf(m, p[c]);
        float s = 0.f;
        for (int c = 0; c < N; c++) { float e = expf(p[c] - m); p[c] = e; s += e; }
        float inv = 1.0f / s;
        for (int c = 0; c < N; c++) p[c] *= inv;
    }
}

// ctx[h][d][e] = sum_c kT[h*16+d][c] * vT[h*16+e][c]
template<int N>
__device__ __forceinline__ void compute_ctx_T(
    const float* __restrict__ kT, const float* __restrict__ vT,
    float* __restrict__ ctx, int tid)
{
    for (int o = tid; o < HEADS * DH * DH; o += NTHREADS) {
        int hh = o >> 8, d = (o >> 4) & 15, e = o & 15;
        const float* kp = kT + (hh * DH + d) * KPAD;
        const float* vp = vT + (hh * DH + e) * KPAD;
        float a = 0.f;
#pragma unroll 4
        for (int c = 0; c < N; c += 2) {
            float2 k2 = *(const float2*)(kp + c);
            float2 v2 = *(const float2*)(vp + c);
            a += k2.x * v2.x + k2.y * v2.y;
        }
        ctx[o] = a;
    }
}

// attn out o[c][col] from Q (stride DPAD) and ctx; write bf16 hi/lo arrays
template<int N>
__device__ __forceinline__ void apply_ctx_split(
    const float* __restrict__ q, const float* __restrict__ ctx,
    __nv_bfloat16* __restrict__ Ahb, __nv_bfloat16* __restrict__ Alb, int tid)
{
    int tx = tid & 31, ty = tid >> 5;
    int hh = tx >> 2;
    int ecol = (tx & 3) * 4;
    for (int c = ty; c < N; c += NWARPS) {
        float4 acc = make_float4(0.f, 0.f, 0.f, 0.f);
        const float* qp = q + c * DPAD + hh * DH;
        const float* cp = ctx + hh * DH * DH + ecol;
#pragma unroll
        for (int d = 0; d < DH; d++) {
            float qv = qp[d];
            float4 cv = *(const float4*)(cp + d * DH);
            acc.x += qv * cv.x; acc.y += qv * cv.y;
            acc.z += qv * cv.z; acc.w += qv * cv.w;
        }
        uint32_t h0, l0, h1, l1;
        split2(acc.x, acc.y, h0, l0);
        split2(acc.z, acc.w, h1, l1);
        int w = hh * 8 + (tx & 3) * 2;
        uint32_t* oh = (uint32_t*)(Ahb + (size_t)c * APAD);
        uint32_t* ol = (uint32_t*)(Alb + (size_t)c * APAD);
        oh[w]     = h0;
        oh[w + 1] = h1;
        ol[w]     = l0;
        ol[w + 1] = l1;
    }
}

// transpose epilogue: dstT[n][c] = D[c][n]
template<int N>
__device__ __forceinline__ void epi_T(const float* __restrict__ D,
                                      float* __restrict__ dstT, int tid)
{
    for (int i = tid; i < N * DIM; i += NTHREADS) {
        int c = i >> 7, n = i & 127;
        dstT[n * KPAD + c] = D[c * DPAD + n];
    }
}

// residual epilogue: h += D [+ bias]
template<int N>
__device__ __forceinline__ void epi_add(float* __restrict__ h,
                                        const float* __restrict__ D,
                                        const float* __restrict__ bias,
                                        bool useBias, int tid)
{
    for (int i = tid; i < N * DIM; i += NTHREADS) {
        int c = i >> 7, n = i & 127;
        h[c * DPAD + n] += D[c * DPAD + n] + (useBias ? bias[n] : 0.f);
    }
}

// FF1 epilogue: gelu(D + bias) -> bf16 hi/lo into t arrays at col offset cofs
template<int N>
__device__ __forceinline__ void epi_ff1(const float* __restrict__ D,
                                        __nv_bfloat16* __restrict__ tHi,
                                        __nv_bfloat16* __restrict__ tLo,
                                        const float* __restrict__ bias,
                                        int cofs, int tid)
{
    for (int i = tid; i < N * DIM; i += NTHREADS) {
        int c = i >> 7, n = i & 127;
        float v = gelu_tanh(D[c * DPAD + n] + bias[n]);
        __nv_bfloat16 hv = __float2bfloat16_rn(v);
        __nv_bfloat16 lv = __float2bfloat16_rn(v - __bfloat162float(hv));
        tHi[(size_t)c * TPAD + cofs + n] = hv;
        tLo[(size_t)c * TPAD + cofs + n] = lv;
    }
}

template<int N>
__device__ __forceinline__ void mean_rows(
    const float* __restrict__ h, float* __restrict__ out, int tid)
{
    if (tid < DIM) {
        float s = 0.f;
        for (int c = 0; c < N; c++) s += h[c * DPAD + tid];
        out[tid] = s * (1.0f / N);
    }
}

// ---------------------------------------------------------------------------
// Weight prep: element-wise bf16 hi/lo split into natural [K][128] planes.
// grid = 72 blocks: (stack-layer 0..7) x (weight 0..8).
// ---------------------------------------------------------------------------
__global__ void prep_kernel(StackParams Pc, StackParams Pt)
{
    int blk = blockIdx.x;
    int sl = blk / 9;       // 0..7
    int wi = blk % 9;       // 0..8
    int stack = sl >> 2, l = sl & 3;
    StackParams P = stack ? Pt : Pc;

    const float* src;
    int ldw, colofs, K;
    size_t dstofs = (size_t)sl * 393216;
    if (wi < 4) {
        const float* base = (wi == 0) ? P.Wq : (wi == 1) ? P.Wk : (wi == 2) ? P.Wv : P.Wo;
        src = base + (size_t)l * DIM * DIM;
        ldw = DIM; colofs = 0; K = DIM;
        dstofs += (size_t)wi * 32768;
    } else if (wi < 8) {
        int j = wi - 4;
        src = P.W1 + (size_t)l * DIM * FFD;
        ldw = FFD; colofs = j * DIM; K = DIM;
        dstofs += 131072 + (size_t)j * 32768;
    } else {
        src = P.W2 + (size_t)l * FFD * DIM;
        ldw = DIM; colofs = 0; K = FFD;
        dstofs += 262144;
    }

    __nv_bfloat16* dst = g_wsplit + dstofs;
    int total = K * DIM;
    for (int i = threadIdx.x; i < total; i += blockDim.x) {
        int k = i >> 7, n = i & 127;
        float w = src[(size_t)k * ldw + colofs + n];
        __nv_bfloat16 hv = __float2bfloat16_rn(w);
        __nv_bfloat16 lv = __float2bfloat16_rn(w - __bfloat162float(hv));
        dst[i] = hv;
        dst[total + i] = lv;
    }
}

// ---------------------------------------------------------------------------
// One CTA = one sequence. Full 4-layer stack in SMEM.
// SMEM floats: h[64*132] | D[64*132] | Ah,Al (bf16 [64][136]) | big | wsm
//   attn: big = kT[128*66] | vT[128*66] | ctx[2048]   (Q lives in D)
//   ff:   big = tHi,tLo (bf16 [64][264])               (two 256-wide halves)
// ---------------------------------------------------------------------------
template<int N, int MODE>
__global__ void __launch_bounds__(NTHREADS, 1)
stack_kernel(const float* __restrict__ xin, float* __restrict__ gout, StackParams P)
{
    extern __shared__ float sm[];
    float*          h   = sm;                                    // 8448 floats
    float*          D   = sm + 64 * DPAD;                        // 8448
    __nv_bfloat16*  Ah  = (__nv_bfloat16*)(sm + 2 * 64 * DPAD);  // 4352 floats
    __nv_bfloat16*  Al  = Ah + 64 * APAD;                        // 4352 floats
    float*          big = sm + 2 * 64 * DPAD + 64 * APAD;        // 18944 floats
    __nv_bfloat16*  wsm = (__nv_bfloat16*)(big + 18944);         // 4096 floats

    float* kT  = big;
    float* vT  = big + DIM * KPAD;
    float* ctx = big + 2 * DIM * KPAD;
    __nv_bfloat16* tHi = (__nv_bfloat16*)big;
    __nv_bfloat16* tLo = tHi + 64 * TPAD;

    const int tid = threadIdx.x;
    const __nv_bfloat16* gstack = g_wsplit + (size_t)MODE * 4 * 393216;
    constexpr int LO128 = 128 * 128;   // lo-plane offset for K=128 blocks
    constexpr int LO512 = 512 * 128;   // lo-plane offset for W2

    // -------- load sequence into h --------
    if (MODE == 0) {
        int sidx = blockIdx.x;
        int b = sidx >> 6, p = sidx & 63;
        const float* xb = xin + (size_t)b * DIM * 62 * 64 + p;
        for (int i = tid; i < N * DIM; i += NTHREADS) {
            int c = i >> 7, e = i & 127;
            h[c * DPAD + e] = xb[(e * 62 + c) * 64];
        }
    } else {
        const float* xb = g_mid + (size_t)blockIdx.x * N * DIM;
        for (int i = tid; i < N * DIM; i += NTHREADS) {
            int c = i >> 7, e = i & 127;
            h[c * DPAD + e] = xb[i];
        }
    }
    __syncthreads();

    for (int l = 0; l < DEPTH; l++) {
        const __nv_bfloat16* gl = gstack + (size_t)l * 393216;
        const float* bo  = P.bo  + l * DIM;
        const float* g1  = P.g1  + l * DIM;
        const float* be1 = P.be1 + l * DIM;
        const float* g2  = P.g2  + l * DIM;
        const float* be2 = P.be2 + l * DIM;
        const float* bf1 = P.bf1 + l * FFD;
        const float* bf2 = P.bf2 + l * DIM;

        // ---- attention ----
        layernorm_split<N>(h, Ah, Al, g1, be1, tid);
        __syncthreads();

        gemm_wmma<8>(Ah, Al, APAD, gl + 32768, LO128, D, wsm, tid);   // K proj
        epi_T<N>(D, kT, tid);
        __syncthreads();

        gemm_wmma<8>(Ah, Al, APAD, gl + 65536, LO128, D, wsm, tid);   // V proj
        epi_T<N>(D, vT, tid);
        __syncthreads();

        gemm_wmma<8>(Ah, Al, APAD, gl, LO128, D, wsm, tid);           // Q proj (stays in D)

        softmax_feat<N>(D, tid);
        softmax_seq_T<N>(kT, tid);
        __syncthreads();

        compute_ctx_T<N>(kT, vT, ctx, tid);
        __syncthreads();

        apply_ctx_split<N>(D, ctx, Ah, Al, tid);
        __syncthreads();

        gemm_wmma<8>(Ah, Al, APAD, gl + 98304, LO128, D, wsm, tid);   // Wo
        epi_add<N>(h, D, bo, true, tid);
        __syncthreads();

        // ---- feed-forward (two 256-wide halves) ----
        layernorm_split<N>(h, Ah, Al, g2, be2, tid);
        __syncthreads();

        for (int half = 0; half < 2; half++) {
            for (int j2 = 0; j2 < 2; j2++) {
                int j = half * 2 + j2;
                gemm_wmma<8>(Ah, Al, APAD, gl + 131072 + (size_t)j * 32768, LO128,
                             D, wsm, tid);
                epi_ff1<N>(D, tHi, tLo, bf1 + j * DIM, j2 * DIM, tid);
                __syncthreads();
            }
            gemm_wmma<16>(tHi, tLo, TPAD, gl + 262144 + (size_t)half * 256 * 128, LO512,
                          D, wsm, tid);
            epi_add<N>(h, D, bf2, half == 1, tid);
            __syncthreads();
        }
    }

    // -------- mean over tokens --------
    if (MODE == 0) {
        mean_rows<N>(h, g_mid + (size_t)blockIdx.x * DIM, tid);
    } else {
        mean_rows<N>(h, gout + (size_t)blockIdx.x * DIM, tid);
    }
}

// ---------------------------------------------------------------------------
static StackParams mk_params(void* const* d_in, int base)
{
    StackParams p;
    p.Wq  = (const float*)d_in[base + 0];
    p.Wk  = (const float*)d_in[base + 1];
    p.Wv  = (const float*)d_in[base + 2];
    p.Wo  = (const float*)d_in[base + 3];
    p.bo  = (const float*)d_in[base + 4];
    p.g1  = (const float*)d_in[base + 5];
    p.be1 = (const float*)d_in[base + 6];
    p.g2  = (const float*)d_in[base + 7];
    p.be2 = (const float*)d_in[base + 8];
    p.W1  = (const float*)d_in[base + 9];
    p.bf1 = (const float*)d_in[base + 10];
    p.W2  = (const float*)d_in[base + 11];
    p.bf2 = (const float*)d_in[base + 12];
    return p;
}

extern "C" void kernel_launch(void* const* d_in, const int* in_sizes, int n_in,
                              void* d_out, int out_size)
{
    (void)in_sizes; (void)n_in; (void)out_size;

    const float* x = (const float*)d_in[0];
    StackParams Pc = mk_params(d_in, 1);
    StackParams Pt = mk_params(d_in, 14);

    // floats: 2*8448 (h,D) + 2*4352 (Ah,Al) + 18944 (big) + 4096 (wsm) = 48640
    const int SMEM = 48640 * (int)sizeof(float);   // 194,560 B

    cudaFuncSetAttribute(stack_kernel<62, 0>,
                         cudaFuncAttributeMaxDynamicSharedMemorySize, SMEM);
    cudaFuncSetAttribute(stack_kernel<64, 1>,
                         cudaFuncAttributeMaxDynamicSharedMemorySize, SMEM);

    // one-time element-wise weight split (no fragment layout assumptions)
    prep_kernel<<<72, NTHREADS>>>(Pc, Pt);

    // channel stack: 4096 sequences of length 62
    stack_kernel<62, 0><<<4096, NTHREADS, SMEM>>>(x, nullptr, Pc);
    // temporal stack: 64 sequences of length 64
    stack_kernel<64, 1><<<64, NTHREADS, SMEM>>>(nullptr, (float*)d_out, Pt);
}

// round 10
// speedup vs baseline: 2.0185x; 2.0185x over previous
#include <cuda_runtime.h>
#include <cuda_bf16.h>
#include <mma.h>
#include <math.h>
#include <stdint.h>

#define DIM      128
#define HEADS    8
#define DH       16
#define FFD      512
#define DEPTH    4
#define EPSV     1e-5f
#define NTHREADS 512
#define NWARPS   16
#define DPAD     132     // fp32 row stride (h, D scratch)
#define APAD     136     // bf16 row stride for A (LN / attn-out) arrays
#define TPAD     264     // bf16 row stride for FF-half intermediate
#define KPAD     66      // fp32 token stride for kT/vT
#define WPAD     136     // bf16 row stride for staged weight slabs (anti-conflict)
#define SLAB_BF  (2 * 16 * WPAD)   // one slab (hi+lo planes), bf16 elems = 4352

// Split weights, natural [K][128] planes: hi plane then lo plane per block.
// Per stack-layer: Wq,Wk,Wv,Wo (2*128*128 each) + W1 j0..3 (2*128*128 each)
// + W2 (2*512*128) = 393216 bf16. 8 stack-layers total.
__device__ __nv_bfloat16 g_wsplit[8 * 393216];

// Intermediate between channel stack and temporal stack
__device__ float g_mid[64 * 64 * DIM];

struct StackParams {
    const float *Wq, *Wk, *Wv, *Wo, *bo;
    const float *g1, *be1, *g2, *be2;
    const float *W1, *bf1, *W2, *bf2;
};

__device__ __forceinline__ float gelu_tanh(float x) {
    float x3 = x * x * x;
    return 0.5f * x * (1.0f + tanhf(0.7978845608028654f * (x + 0.044715f * x3)));
}

// pack (a,b) -> hi word (bf16(a) low half, bf16(b) high half) + lo word (residuals)
__device__ __forceinline__ void split2(float a, float b, uint32_t& hi, uint32_t& lo) {
    __nv_bfloat16 ah = __float2bfloat16_rn(a);
    __nv_bfloat16 bh = __float2bfloat16_rn(b);
    __nv_bfloat16 al = __float2bfloat16_rn(a - __bfloat162float(ah));
    __nv_bfloat16 bl = __float2bfloat16_rn(b - __bfloat162float(bh));
    hi = ((uint32_t)__bfloat16_as_ushort(bh) << 16) | (uint32_t)__bfloat16_as_ushort(ah);
    lo = ((uint32_t)__bfloat16_as_ushort(bl) << 16) | (uint32_t)__bfloat16_as_ushort(al);
}

// ---------------- cp.async helpers ----------------
__device__ __forceinline__ void cp16(void* dst, const void* src) {
    uint32_t d = (uint32_t)__cvta_generic_to_shared(dst);
    asm volatile("cp.async.ca.shared.global [%0], [%1], 16;" :: "r"(d), "l"(src));
}
__device__ __forceinline__ void cp_commit() { asm volatile("cp.async.commit_group;"); }
__device__ __forceinline__ void cp_wait0()  { asm volatile("cp.async.wait_group 0;"); }

// Stage one weight slab (16 k-rows x 128 cols, hi plane then lo plane) into
// smem with PADDED row stride WPAD (272B) so B ldmatrix rows land in distinct
// bank groups. 512 threads: plane = t>>8, row = (t>>4)&15, chunk16 = t&15.
__device__ __forceinline__ void stage_slab(__nv_bfloat16* dst, const __nv_bfloat16* gW,
                                           int slab, int loOfs, int tid)
{
    int plane = tid >> 8;          // 0 = hi, 1 = lo
    int row   = (tid >> 4) & 15;
    int chunk = tid & 15;          // 16B chunks across 128 cols
    const __nv_bfloat16* src = gW + (plane ? loOfs : 0)
                             + (size_t)slab * 2048 + row * 128 + chunk * 8;
    cp16(dst + plane * (16 * WPAD) + row * WPAD + chunk * 8, src);
}

// ---------------------------------------------------------------------------
// wmma GEMM: D[64 x 128] = A @ W with K = 16*KSLABS.
// A = hi/lo bf16 arrays, row-major, leading dim lda (tokens x K).
// W streamed from g_wsplit (natural [K][128] planes) via cp.async dbl buffer
// into WPAD-padded smem slabs (conflict-free ldmatrix).
// 16 warps: row strip = wy&3 (16 tokens), col group = wy>>2 (32 cols).
// 3-term split: D = Ah*Wh + Ah*Wl + Al*Wh (fp32 accum). Result -> D scratch.
// Ends with __syncthreads().
// ---------------------------------------------------------------------------
template<int KSLABS>
__device__ __forceinline__ void gemm_wmma(
    const __nv_bfloat16* __restrict__ Ah, const __nv_bfloat16* __restrict__ Al, int lda,
    const __nv_bfloat16* __restrict__ gW, int loOfs,
    float* __restrict__ D, __nv_bfloat16* __restrict__ wsm, int tid)
{
    using namespace nvcuda::wmma;
    const int wy   = tid >> 5;
    const int mrow = wy & 3;
    const int ngrp = wy >> 2;

    fragment<accumulator, 16, 16, 16, float> c0, c1;
    fill_fragment(c0, 0.f);
    fill_fragment(c1, 0.f);

    stage_slab(wsm, gW, 0, loOfs, tid);
    cp_commit();

    for (int s = 0; s < KSLABS; s++) {
        cp_wait0();
        __syncthreads();
        if (s + 1 < KSLABS) {
            stage_slab(wsm + ((s + 1) & 1) * SLAB_BF, gW, s + 1, loOfs, tid);
            cp_commit();
        }
        const __nv_bfloat16* ws = wsm + (s & 1) * SLAB_BF;
        const __nv_bfloat16* wlo = ws + 16 * WPAD;

        fragment<matrix_a, 16, 16, 16, __nv_bfloat16, row_major> ah, al;
        load_matrix_sync(ah, Ah + (size_t)(mrow * 16) * lda + s * 16, lda);
        load_matrix_sync(al, Al + (size_t)(mrow * 16) * lda + s * 16, lda);

        fragment<matrix_b, 16, 16, 16, __nv_bfloat16, row_major> bh, bl;
        load_matrix_sync(bh, ws  + ngrp * 32, WPAD);
        load_matrix_sync(bl, wlo + ngrp * 32, WPAD);
        mma_sync(c0, ah, bh, c0);
        mma_sync(c0, ah, bl, c0);
        mma_sync(c0, al, bh, c0);

        load_matrix_sync(bh, ws  + ngrp * 32 + 16, WPAD);
        load_matrix_sync(bl, wlo + ngrp * 32 + 16, WPAD);
        mma_sync(c1, ah, bh, c1);
        mma_sync(c1, ah, bl, c1);
        mma_sync(c1, al, bh, c1);
    }

    store_matrix_sync(D + (size_t)(mrow * 16) * DPAD + ngrp * 32,      c0, DPAD, mem_row_major);
    store_matrix_sync(D + (size_t)(mrow * 16) * DPAD + ngrp * 32 + 16, c1, DPAD, mem_row_major);
    __syncthreads();
}

// ---------------------------------------------------------------------------
// LayerNorm: reads h [N][DPAD] fp32, writes bf16 hi/lo arrays [N][APAD].
template<int N>
__device__ __forceinline__ void layernorm_split(
    const float* __restrict__ src, __nv_bfloat16* __restrict__ Ahb,
    __nv_bfloat16* __restrict__ Alb,
    const float* __restrict__ g, const float* __restrict__ b, int tid)
{
    int lane = tid & 31, wid = tid >> 5;
    float4 g4 = *(const float4*)(g + lane * 4);
    float4 b4 = *(const float4*)(b + lane * 4);
    for (int c = wid; c < N; c += NWARPS) {
        float4 x = *(const float4*)(src + c * DPAD + lane * 4);
        float s = x.x + x.y + x.z + x.w;
#pragma unroll
        for (int o = 16; o; o >>= 1) s += __shfl_xor_sync(0xffffffffu, s, o);
        float m = s * (1.0f / DIM);
        float dx = x.x - m, dy = x.y - m, dz = x.z - m, dw = x.w - m;
        float v = dx * dx + dy * dy + dz * dz + dw * dw;
#pragma unroll
        for (int o = 16; o; o >>= 1) v += __shfl_xor_sync(0xffffffffu, v, o);
        float rs = rsqrtf(v * (1.0f / DIM) + EPSV);
        float v0 = dx * rs * g4.x + b4.x;
        float v1 = dy * rs * g4.y + b4.y;
        float v2 = dz * rs * g4.z + b4.z;
        float v3 = dw * rs * g4.w + b4.w;
        uint32_t h0, l0, h1, l1;
        split2(v0, v1, h0, l0);
        split2(v2, v3, h1, l1);
        uint32_t* oh = (uint32_t*)(Ahb + (size_t)c * APAD);
        uint32_t* ol = (uint32_t*)(Alb + (size_t)c * APAD);
        oh[lane * 2]     = h0;
        oh[lane * 2 + 1] = h1;
        ol[lane * 2]     = l0;
        ol[lane * 2 + 1] = l1;
    }
}

// softmax over the 16-feature head dim on Q (= D scratch, stride DPAD)
template<int N>
__device__ __forceinline__ void softmax_feat(float* __restrict__ q, int tid)
{
    int lane = tid & 31, wid = tid >> 5;
    for (int c = wid; c < N; c += NWARPS) {
        float4 x = *(const float4*)(q + c * DPAD + lane * 4);
        float m = fmaxf(fmaxf(x.x, x.y), fmaxf(x.z, x.w));
        m = fmaxf(m, __shfl_xor_sync(0xffffffffu, m, 1));
        m = fmaxf(m, __shfl_xor_sync(0xffffffffu, m, 2));
        float4 e;
        e.x = expf(x.x - m); e.y = expf(x.y - m);
        e.z = expf(x.z - m); e.w = expf(x.w - m);
        float s = e.x + e.y + e.z + e.w;
        s += __shfl_xor_sync(0xffffffffu, s, 1);
        s += __shfl_xor_sync(0xffffffffu, s, 2);
        float sc = 0.25f / s;
        e.x *= sc; e.y *= sc; e.z *= sc; e.w *= sc;
        *(float4*)(q + c * DPAD + lane * 4) = e;
    }
}

// softmax over the sequence dim on kT [128][KPAD]
template<int N>
__device__ __forceinline__ void softmax_seq_T(float* __restrict__ kT, int tid)
{
    if (tid < DIM) {
        float* p = kT + tid * KPAD;
        float m = -1e30f;
        for (int c = 0; c < N; c++) m = fmaxf(m, p[c]);
        float s = 0.f;
        for (int c = 0; c < N; c++) { float e = expf(p[c] - m); p[c] = e; s += e; }
        float inv = 1.0f / s;
        for (int c = 0; c < N; c++) p[c] *= inv;
    }
}

// ctx[h][d][e] = sum_c kT[h*16+d][c] * vT[h*16+e][c]
template<int N>
__device__ __forceinline__ void compute_ctx_T(
    const float* __restrict__ kT, const float* __restrict__ vT,
    float* __restrict__ ctx, int tid)
{
    for (int o = tid; o < HEADS * DH * DH; o += NTHREADS) {
        int hh = o >> 8, d = (o >> 4) & 15, e = o & 15;
        const float* kp = kT + (hh * DH + d) * KPAD;
        const float* vp = vT + (hh * DH + e) * KPAD;
        float a = 0.f;
#pragma unroll 4
        for (int c = 0; c < N; c += 2) {
            float2 k2 = *(const float2*)(kp + c);
            float2 v2 = *(const float2*)(vp + c);
            a += k2.x * v2.x + k2.y * v2.y;
        }
        ctx[o] = a;
    }
}

// attn out o[c][col] from Q (stride DPAD) and ctx; write bf16 hi/lo arrays
template<int N>
__device__ __forceinline__ void apply_ctx_split(
    const float* __restrict__ q, const float* __restrict__ ctx,
    __nv_bfloat16* __restrict__ Ahb, __nv_bfloat16* __restrict__ Alb, int tid)
{
    int tx = tid & 31, ty = tid >> 5;
    int hh = tx >> 2;
    int ecol = (tx & 3) * 4;
    for (int c = ty; c < N; c += NWARPS) {
        float4 acc = make_float4(0.f, 0.f, 0.f, 0.f);
        const float* qp = q + c * DPAD + hh * DH;
        const float* cp = ctx + hh * DH * DH + ecol;
#pragma unroll
        for (int d = 0; d < DH; d++) {
            float qv = qp[d];
            float4 cv = *(const float4*)(cp + d * DH);
            acc.x += qv * cv.x; acc.y += qv * cv.y;
            acc.z += qv * cv.z; acc.w += qv * cv.w;
        }
        uint32_t h0, l0, h1, l1;
        split2(acc.x, acc.y, h0, l0);
        split2(acc.z, acc.w, h1, l1);
        int w = hh * 8 + (tx & 3) * 2;
        uint32_t* oh = (uint32_t*)(Ahb + (size_t)c * APAD);
        uint32_t* ol = (uint32_t*)(Alb + (size_t)c * APAD);
        oh[w]     = h0;
        oh[w + 1] = h1;
        ol[w]     = l0;
        ol[w + 1] = l1;
    }
}

// transpose epilogue: dstT[n][c] = D[c][n]
template<int N>
__device__ __forceinline__ void epi_T(const float* __restrict__ D,
                                      float* __restrict__ dstT, int tid)
{
    for (int i = tid; i < N * DIM; i += NTHREADS) {
        int c = i >> 7, n = i & 127;
        dstT[n * KPAD + c] = D[c * DPAD + n];
    }
}

// residual epilogue: h += D [+ bias]
template<int N>
__device__ __forceinline__ void epi_add(float* __restrict__ h,
                                        const float* __restrict__ D,
                                        const float* __restrict__ bias,
                                        bool useBias, int tid)
{
    for (int i = tid; i < N * DIM; i += NTHREADS) {
        int c = i >> 7, n = i & 127;
        h[c * DPAD + n] += D[c * DPAD + n] + (useBias ? bias[n] : 0.f);
    }
}

// FF1 epilogue: gelu(D + bias) -> bf16 hi/lo into t arrays at col offset cofs
template<int N>
__device__ __forceinline__ void epi_ff1(const float* __restrict__ D,
                                        __nv_bfloat16* __restrict__ tHi,
                                        __nv_bfloat16* __restrict__ tLo,
                                        const float* __restrict__ bias,
                                        int cofs, int tid)
{
    for (int i = tid; i < N * DIM; i += NTHREADS) {
        int c = i >> 7, n = i & 127;
        float v = gelu_tanh(D[c * DPAD + n] + bias[n]);
        __nv_bfloat16 hv = __float2bfloat16_rn(v);
        __nv_bfloat16 lv = __float2bfloat16_rn(v - __bfloat162float(hv));
        tHi[(size_t)c * TPAD + cofs + n] = hv;
        tLo[(size_t)c * TPAD + cofs + n] = lv;
    }
}

template<int N>
__device__ __forceinline__ void mean_rows(
    const float* __restrict__ h, float* __restrict__ out, int tid)
{
    if (tid < DIM) {
        float s = 0.f;
        for (int c = 0; c < N; c++) s += h[c * DPAD + tid];
        out[tid] = s * (1.0f / N);
    }
}

// ---------------------------------------------------------------------------
// Weight prep: element-wise bf16 hi/lo split into natural [K][128] planes.
// grid = 72 blocks: (stack-layer 0..7) x (weight 0..8).
// ---------------------------------------------------------------------------
__global__ void prep_kernel(StackParams Pc, StackParams Pt)
{
    int blk = blockIdx.x;
    int sl = blk / 9;       // 0..7
    int wi = blk % 9;       // 0..8
    int stack = sl >> 2, l = sl & 3;
    StackParams P = stack ? Pt : Pc;

    const float* src;
    int ldw, colofs, K;
    size_t dstofs = (size_t)sl * 393216;
    if (wi < 4) {
        const float* base = (wi == 0) ? P.Wq : (wi == 1) ? P.Wk : (wi == 2) ? P.Wv : P.Wo;
        src = base + (size_t)l * DIM * DIM;
        ldw = DIM; colofs = 0; K = DIM;
        dstofs += (size_t)wi * 32768;
    } else if (wi < 8) {
        int j = wi - 4;
        src = P.W1 + (size_t)l * DIM * FFD;
        ldw = FFD; colofs = j * DIM; K = DIM;
        dstofs += 131072 + (size_t)j * 32768;
    } else {
        src = P.W2 + (size_t)l * FFD * DIM;
        ldw = DIM; colofs = 0; K = FFD;
        dstofs += 262144;
    }

    __nv_bfloat16* dst = g_wsplit + dstofs;
    int total = K * DIM;
    for (int i = threadIdx.x; i < total; i += blockDim.x) {
        int k = i >> 7, n = i & 127;
        float w = src[(size_t)k * ldw + colofs + n];
        __nv_bfloat16 hv = __float2bfloat16_rn(w);
        __nv_bfloat16 lv = __float2bfloat16_rn(w - __bfloat162float(hv));
        dst[i] = hv;
        dst[total + i] = lv;
    }
}

// ---------------------------------------------------------------------------
// One CTA = one sequence. Full 4-layer stack in SMEM.
// SMEM floats: h[64*132] | D[64*132] | Ah,Al (bf16 [64][136]) | big | wsm
//   attn: big = kT[128*66] | vT[128*66] | ctx[2048]   (Q lives in D)
//   ff:   big = tHi,tLo (bf16 [64][264])               (two 256-wide halves)
// ---------------------------------------------------------------------------
template<int N, int MODE>
__global__ void __launch_bounds__(NTHREADS, 1)
stack_kernel(const float* __restrict__ xin, float* __restrict__ gout, StackParams P)
{
    extern __shared__ float sm[];
    float*          h   = sm;                                    // 8448 floats
    float*          D   = sm + 64 * DPAD;                        // 8448
    __nv_bfloat16*  Ah  = (__nv_bfloat16*)(sm + 2 * 64 * DPAD);  // 4352 floats
    __nv_bfloat16*  Al  = Ah + 64 * APAD;                        // 4352 floats
    float*          big = sm + 2 * 64 * DPAD + 64 * APAD;        // 18944 floats
    __nv_bfloat16*  wsm = (__nv_bfloat16*)(big + 18944);         // 2*SLAB_BF bf16 = 4352 floats

    float* kT  = big;
    float* vT  = big + DIM * KPAD;
    float* ctx = big + 2 * DIM * KPAD;
    __nv_bfloat16* tHi = (__nv_bfloat16*)big;
    __nv_bfloat16* tLo = tHi + 64 * TPAD;

    const int tid = threadIdx.x;
    const __nv_bfloat16* gstack = g_wsplit + (size_t)MODE * 4 * 393216;
    constexpr int LO128 = 128 * 128;   // lo-plane offset for K=128 blocks
    constexpr int LO512 = 512 * 128;   // lo-plane offset for W2

    // -------- load sequence into h --------
    if (MODE == 0) {
        int sidx = blockIdx.x;
        int b = sidx >> 6, p = sidx & 63;
        const float* xb = xin + (size_t)b * DIM * 62 * 64 + p;
        for (int i = tid; i < N * DIM; i += NTHREADS) {
            int c = i >> 7, e = i & 127;
            h[c * DPAD + e] = xb[(e * 62 + c) * 64];
        }
    } else {
        const float* xb = g_mid + (size_t)blockIdx.x * N * DIM;
        for (int i = tid; i < N * DIM; i += NTHREADS) {
            int c = i >> 7, e = i & 127;
            h[c * DPAD + e] = xb[i];
        }
    }
    __syncthreads();

    for (int l = 0; l < DEPTH; l++) {
        const __nv_bfloat16* gl = gstack + (size_t)l * 393216;
        const float* bo  = P.bo  + l * DIM;
        const float* g1  = P.g1  + l * DIM;
        const float* be1 = P.be1 + l * DIM;
        const float* g2  = P.g2  + l * DIM;
        const float* be2 = P.be2 + l * DIM;
        const float* bf1 = P.bf1 + l * FFD;
        const float* bf2 = P.bf2 + l * DIM;

        // ---- attention ----
        layernorm_split<N>(h, Ah, Al, g1, be1, tid);
        __syncthreads();

        gemm_wmma<8>(Ah, Al, APAD, gl + 32768, LO128, D, wsm, tid);   // K proj
        epi_T<N>(D, kT, tid);
        __syncthreads();

        gemm_wmma<8>(Ah, Al, APAD, gl + 65536, LO128, D, wsm, tid);   // V proj
        epi_T<N>(D, vT, tid);
        __syncthreads();

        gemm_wmma<8>(Ah, Al, APAD, gl, LO128, D, wsm, tid);           // Q proj (stays in D)

        softmax_feat<N>(D, tid);
        softmax_seq_T<N>(kT, tid);
        __syncthreads();

        compute_ctx_T<N>(kT, vT, ctx, tid);
        __syncthreads();

        apply_ctx_split<N>(D, ctx, Ah, Al, tid);
        __syncthreads();

        gemm_wmma<8>(Ah, Al, APAD, gl + 98304, LO128, D, wsm, tid);   // Wo
        epi_add<N>(h, D, bo, true, tid);
        __syncthreads();

        // ---- feed-forward (two 256-wide halves) ----
        layernorm_split<N>(h, Ah, Al, g2, be2, tid);
        __syncthreads();

        for (int half = 0; half < 2; half++) {
            for (int j2 = 0; j2 < 2; j2++) {
                int j = half * 2 + j2;
                gemm_wmma<8>(Ah, Al, APAD, gl + 131072 + (size_t)j * 32768, LO128,
                             D, wsm, tid);
                epi_ff1<N>(D, tHi, tLo, bf1 + j * DIM, j2 * DIM, tid);
                __syncthreads();
            }
            gemm_wmma<16>(tHi, tLo, TPAD, gl + 262144 + (size_t)half * 256 * 128, LO512,
                          D, wsm, tid);
            epi_add<N>(h, D, bf2, half == 1, tid);
            __syncthreads();
        }
    }

    // -------- mean over tokens --------
    if (MODE == 0) {
        mean_rows<N>(h, g_mid + (size_t)blockIdx.x * DIM, tid);
    } else {
        mean_rows<N>(h, gout + (size_t)blockIdx.x * DIM, tid);
    }
}

// ---------------------------------------------------------------------------
static StackParams mk_params(void* const* d_in, int base)
{
    StackParams p;
    p.Wq  = (const float*)d_in[base + 0];
    p.Wk  = (const float*)d_in[base + 1];
    p.Wv  = (const float*)d_in[base + 2];
    p.Wo  = (const float*)d_in[base + 3];
    p.bo  = (const float*)d_in[base + 4];
    p.g1  = (const float*)d_in[base + 5];
    p.be1 = (const float*)d_in[base + 6];
    p.g2  = (const float*)d_in[base + 7];
    p.be2 = (const float*)d_in[base + 8];
    p.W1  = (const float*)d_in[base + 9];
    p.bf1 = (const float*)d_in[base + 10];
    p.W2  = (const float*)d_in[base + 11];
    p.bf2 = (const float*)d_in[base + 12];
    return p;
}

extern "C" void kernel_launch(void* const* d_in, const int* in_sizes, int n_in,
                              void* d_out, int out_size)
{
    (void)in_sizes; (void)n_in; (void)out_size;

    const float* x = (const float*)d_in[0];
    StackParams Pc = mk_params(d_in, 1);
    StackParams Pt = mk_params(d_in, 14);

    // floats: 2*8448 (h,D) + 2*4352 (Ah,Al) + 18944 (big) + 4352 (wsm) = 48896
    const int SMEM = 48896 * (int)sizeof(float);   // 195,584 B

    cudaFuncSetAttribute(stack_kernel<62, 0>,
                         cudaFuncAttributeMaxDynamicSharedMemorySize, SMEM);
    cudaFuncSetAttribute(stack_kernel<64, 1>,
                         cudaFuncAttributeMaxDynamicSharedMemorySize, SMEM);

    // one-time element-wise weight split (no fragment layout assumptions)
    prep_kernel<<<72, NTHREADS>>>(Pc, Pt);

    // channel stack: 4096 sequences of length 62
    stack_kernel<62, 0><<<4096, NTHREADS, SMEM>>>(x, nullptr, Pc);
    // temporal stack: 64 sequences of length 64
    stack_kernel<64, 1><<<64, NTHREADS, SMEM>>>(nullptr, (float*)d_out, Pt);
}

// round 14
// speedup vs baseline: 2.0381x; 1.0097x over previous
#include <cuda_runtime.h>
#include <cuda_bf16.h>
#include <mma.h>
#include <math.h>
#include <stdint.h>

#define DIM      128
#define HEADS    8
#define DH       16
#define FFD      512
#define DEPTH    4
#define EPSV     1e-5f
#define NTHREADS 512
#define NWARPS   16
#define DPAD     132     // fp32 row stride (h, D scratch)
#define APAD     136     // bf16 row stride for A (LN / attn-out) arrays
#define TPAD     264     // bf16 row stride for FF-half intermediate
#define KPAD     68      // fp32 token stride for kT/vT (ldm%4==0 for col-major store)
#define WPAD     136     // bf16 row stride for staged weight slabs (anti-conflict)
#define SLABW    (2 * 16 * WPAD)    // one weight, 16 k-rows, hi+lo = 4352 bf16
#define QKVSLAB  (3 * SLABW)        // 13056 bf16
#define SLAB32   (2 * 32 * WPAD)    // one weight, 32 k-rows, hi+lo = 8704 bf16

// Split weights, natural [K][128] planes: hi plane then lo plane per block.
// Per stack-layer: Wq,Wk,Wv,Wo (2*128*128 each) + W1 j0..3 (2*128*128 each)
// + W2 (2*512*128) = 393216 bf16. 8 stack-layers total.
__device__ __nv_bfloat16 g_wsplit[8 * 393216];

// Intermediate between channel stack and temporal stack
__device__ float g_mid[64 * 64 * DIM];

struct StackParams {
    const float *Wq, *Wk, *Wv, *Wo, *bo;
    const float *g1, *be1, *g2, *be2;
    const float *W1, *bf1, *W2, *bf2;
};

__device__ __forceinline__ float gelu_tanh(float x) {
    float x3 = x * x * x;
    return 0.5f * x * (1.0f + tanhf(0.7978845608028654f * (x + 0.044715f * x3)));
}

// pack (a,b) -> hi word (bf16(a) low half, bf16(b) high half) + lo word (residuals)
__device__ __forceinline__ void split2(float a, float b, uint32_t& hi, uint32_t& lo) {
    __nv_bfloat16 ah = __float2bfloat16_rn(a);
    __nv_bfloat16 bh = __float2bfloat16_rn(b);
    __nv_bfloat16 al = __float2bfloat16_rn(a - __bfloat162float(ah));
    __nv_bfloat16 bl = __float2bfloat16_rn(b - __bfloat162float(bh));
    hi = ((uint32_t)__bfloat16_as_ushort(bh) << 16) | (uint32_t)__bfloat16_as_ushort(ah);
    lo = ((uint32_t)__bfloat16_as_ushort(bl) << 16) | (uint32_t)__bfloat16_as_ushort(al);
}

// ---------------- cp.async helpers ----------------
__device__ __forceinline__ void cp16(void* dst, const void* src) {
    uint32_t d = (uint32_t)__cvta_generic_to_shared(dst);
    asm volatile("cp.async.ca.shared.global [%0], [%1], 16;" :: "r"(d), "l"(src));
}
__device__ __forceinline__ void cp_commit() { asm volatile("cp.async.commit_group;"); }
__device__ __forceinline__ void cp_wait0()  { asm volatile("cp.async.wait_group 0;"); }

// Stage one 16-row slab for THREE weights (Q,K,V) into padded smem.
// Per weight: 2 planes x 16 rows x 16 chunks = 512 x 16B. 512 threads, 3 cp16 each.
__device__ __forceinline__ void stage_qkv(__nv_bfloat16* dst,
                                          const __nv_bfloat16* g0,
                                          const __nv_bfloat16* g1,
                                          const __nv_bfloat16* g2,
                                          int slab, int loOfs, int tid)
{
    int plane = tid >> 8;
    int row   = (tid >> 4) & 15;
    int chunk = tid & 15;
    size_t sofs = (size_t)(plane ? loOfs : 0) + (size_t)slab * 2048 + row * 128 + chunk * 8;
    int dofs = plane * (16 * WPAD) + row * WPAD + chunk * 8;
    cp16(dst + dofs,             g0 + sofs);
    cp16(dst + SLABW + dofs,     g1 + sofs);
    cp16(dst + 2 * SLABW + dofs, g2 + sofs);
}

// Stage one 32-row slab for one weight. 2 planes x 32 rows x 16 chunks = 1024 x 16B.
__device__ __forceinline__ void stage32(__nv_bfloat16* dst, const __nv_bfloat16* gW,
                                        int slab, int loOfs, int tid)
{
#pragma unroll
    for (int i = tid; i < 1024; i += NTHREADS) {
        int plane = i >> 9;
        int row   = (i >> 4) & 31;
        int chunk = i & 15;
        const __nv_bfloat16* src = gW + (size_t)(plane ? loOfs : 0)
                                 + (size_t)slab * 4096 + row * 128 + chunk * 8;
        cp16(dst + plane * (32 * WPAD) + row * WPAD + chunk * 8, src);
    }
}

// ---------------------------------------------------------------------------
// Fused QKV GEMM: for one A (LN output, hi/lo), compute Q->D (row-major),
// K->kT and V->vT (transposed via col-major store). K = 128 (8 k16 slabs).
// 16 warps: mrow = wy&3 (16-token strip), ngrp = wy>>2 (32-col group).
// 3-term split per weight: Ah*Wh + Ah*Wl + Al*Wh. Ends with __syncthreads().
// ---------------------------------------------------------------------------
__device__ __forceinline__ void gemm_qkv(
    const __nv_bfloat16* __restrict__ Ah, const __nv_bfloat16* __restrict__ Al,
    const __nv_bfloat16* __restrict__ gq, const __nv_bfloat16* __restrict__ gk,
    const __nv_bfloat16* __restrict__ gv, int loOfs,
    float* __restrict__ D, float* __restrict__ kT, float* __restrict__ vT,
    __nv_bfloat16* __restrict__ wsm, int tid)
{
    using namespace nvcuda::wmma;
    const int wy   = tid >> 5;
    const int mrow = wy & 3;
    const int ngrp = wy >> 2;

    fragment<accumulator, 16, 16, 16, float> acc[3][2];
#pragma unroll
    for (int w = 0; w < 3; w++) {
        fill_fragment(acc[w][0], 0.f);
        fill_fragment(acc[w][1], 0.f);
    }

    stage_qkv(wsm, gq, gk, gv, 0, loOfs, tid);
    cp_commit();

    for (int s = 0; s < 8; s++) {
        cp_wait0();
        __syncthreads();
        if (s + 1 < 8) {
            stage_qkv(wsm + ((s + 1) & 1) * QKVSLAB, gq, gk, gv, s + 1, loOfs, tid);
            cp_commit();
        }
        const __nv_bfloat16* base = wsm + (s & 1) * QKVSLAB;

        fragment<matrix_a, 16, 16, 16, __nv_bfloat16, row_major> ah, al;
        load_matrix_sync(ah, Ah + (size_t)(mrow * 16) * APAD + s * 16, APAD);
        load_matrix_sync(al, Al + (size_t)(mrow * 16) * APAD + s * 16, APAD);

#pragma unroll
        for (int w = 0; w < 3; w++) {
            const __nv_bfloat16* ws  = base + w * SLABW;
            const __nv_bfloat16* wlo = ws + 16 * WPAD;
            fragment<matrix_b, 16, 16, 16, __nv_bfloat16, row_major> bh, bl;

            load_matrix_sync(bh, ws  + ngrp * 32, WPAD);
            load_matrix_sync(bl, wlo + ngrp * 32, WPAD);
            mma_sync(acc[w][0], ah, bh, acc[w][0]);
            mma_sync(acc[w][0], ah, bl, acc[w][0]);
            mma_sync(acc[w][0], al, bh, acc[w][0]);

            load_matrix_sync(bh, ws  + ngrp * 32 + 16, WPAD);
            load_matrix_sync(bl, wlo + ngrp * 32 + 16, WPAD);
            mma_sync(acc[w][1], ah, bh, acc[w][1]);
            mma_sync(acc[w][1], ah, bl, acc[w][1]);
            mma_sync(acc[w][1], al, bh, acc[w][1]);
        }
    }

    // Q row-major into D
    store_matrix_sync(D + (size_t)(mrow * 16) * DPAD + ngrp * 32,      acc[0][0], DPAD, mem_row_major);
    store_matrix_sync(D + (size_t)(mrow * 16) * DPAD + ngrp * 32 + 16, acc[0][1], DPAD, mem_row_major);
    // K, V transposed (col-major): element (tok i, col j) -> kT[(c0+j)*KPAD + m0+i]
    store_matrix_sync(kT + (size_t)(ngrp * 32) * KPAD + mrow * 16,        acc[1][0], KPAD, mem_col_major);
    store_matrix_sync(kT + (size_t)(ngrp * 32 + 16) * KPAD + mrow * 16,   acc[1][1], KPAD, mem_col_major);
    store_matrix_sync(vT + (size_t)(ngrp * 32) * KPAD + mrow * 16,        acc[2][0], KPAD, mem_col_major);
    store_matrix_sync(vT + (size_t)(ngrp * 32 + 16) * KPAD + mrow * 16,   acc[2][1], KPAD, mem_col_major);
    __syncthreads();
}

// ---------------------------------------------------------------------------
// 32-deep-slab GEMM: D[64 x 128] = A @ W, K = 32*KSLABS. Result -> D scratch.
// Ends with __syncthreads().
// ---------------------------------------------------------------------------
template<int KSLABS>
__device__ __forceinline__ void gemm32(
    const __nv_bfloat16* __restrict__ Ah, const __nv_bfloat16* __restrict__ Al, int lda,
    const __nv_bfloat16* __restrict__ gW, int loOfs,
    float* __restrict__ D, __nv_bfloat16* __restrict__ wsm, int tid)
{
    using namespace nvcuda::wmma;
    const int wy   = tid >> 5;
    const int mrow = wy & 3;
    const int ngrp = wy >> 2;

    fragment<accumulator, 16, 16, 16, float> c0, c1;
    fill_fragment(c0, 0.f);
    fill_fragment(c1, 0.f);

    stage32(wsm, gW, 0, loOfs, tid);
    cp_commit();

    for (int s = 0; s < KSLABS; s++) {
        cp_wait0();
        __syncthreads();
        if (s + 1 < KSLABS) {
            stage32(wsm + ((s + 1) & 1) * SLAB32, gW, s + 1, loOfs, tid);
            cp_commit();
        }
        const __nv_bfloat16* ws = wsm + (s & 1) * SLAB32;

#pragma unroll
        for (int sub = 0; sub < 2; sub++) {
            const __nv_bfloat16* wk  = ws + sub * 16 * WPAD;
            const __nv_bfloat16* wlo = wk + 32 * WPAD;     // lo plane, same sub offset
            int k = s * 32 + sub * 16;

            fragment<matrix_a, 16, 16, 16, __nv_bfloat16, row_major> ah, al;
            load_matrix_sync(ah, Ah + (size_t)(mrow * 16) * lda + k, lda);
            load_matrix_sync(al, Al + (size_t)(mrow * 16) * lda + k, lda);

            fragment<matrix_b, 16, 16, 16, __nv_bfloat16, row_major> bh, bl;
            load_matrix_sync(bh, wk  + ngrp * 32, WPAD);
            load_matrix_sync(bl, wlo + ngrp * 32, WPAD);
            mma_sync(c0, ah, bh, c0);
            mma_sync(c0, ah, bl, c0);
            mma_sync(c0, al, bh, c0);

            load_matrix_sync(bh, wk  + ngrp * 32 + 16, WPAD);
            load_matrix_sync(bl, wlo + ngrp * 32 + 16, WPAD);
            mma_sync(c1, ah, bh, c1);
            mma_sync(c1, ah, bl, c1);
            mma_sync(c1, al, bh, c1);
        }
    }

    store_matrix_sync(D + (size_t)(mrow * 16) * DPAD + ngrp * 32,      c0, DPAD, mem_row_major);
    store_matrix_sync(D + (size_t)(mrow * 16) * DPAD + ngrp * 32 + 16, c1, DPAD, mem_row_major);
    __syncthreads();
}

// ---------------------------------------------------------------------------
// LayerNorm: reads h [N][DPAD] fp32, writes bf16 hi/lo arrays [N][APAD].
template<int N>
__device__ __forceinline__ void layernorm_split(
    const float* __restrict__ src, __nv_bfloat16* __restrict__ Ahb,
    __nv_bfloat16* __restrict__ Alb,
    const float* __restrict__ g, const float* __restrict__ b, int tid)
{
    int lane = tid & 31, wid = tid >> 5;
    float4 g4 = *(const float4*)(g + lane * 4);
    float4 b4 = *(const float4*)(b + lane * 4);
    for (int c = wid; c < N; c += NWARPS) {
        float4 x = *(const float4*)(src + c * DPAD + lane * 4);
        float s = x.x + x.y + x.z + x.w;
#pragma unroll
        for (int o = 16; o; o >>= 1) s += __shfl_xor_sync(0xffffffffu, s, o);
        float m = s * (1.0f / DIM);
        float dx = x.x - m, dy = x.y - m, dz = x.z - m, dw = x.w - m;
        float v = dx * dx + dy * dy + dz * dz + dw * dw;
#pragma unroll
        for (int o = 16; o; o >>= 1) v += __shfl_xor_sync(0xffffffffu, v, o);
        float rs = rsqrtf(v * (1.0f / DIM) + EPSV);
        float v0 = dx * rs * g4.x + b4.x;
        float v1 = dy * rs * g4.y + b4.y;
        float v2 = dz * rs * g4.z + b4.z;
        float v3 = dw * rs * g4.w + b4.w;
        uint32_t h0, l0, h1, l1;
        split2(v0, v1, h0, l0);
        split2(v2, v3, h1, l1);
        uint32_t* oh = (uint32_t*)(Ahb + (size_t)c * APAD);
        uint32_t* ol = (uint32_t*)(Alb + (size_t)c * APAD);
        oh[lane * 2]     = h0;
        oh[lane * 2 + 1] = h1;
        ol[lane * 2]     = l0;
        ol[lane * 2 + 1] = l1;
    }
}

// softmax over the 16-feature head dim on Q (= D scratch, stride DPAD)
template<int N>
__device__ __forceinline__ void softmax_feat(float* __restrict__ q, int tid)
{
    int lane = tid & 31, wid = tid >> 5;
    for (int c = wid; c < N; c += NWARPS) {
        float4 x = *(const float4*)(q + c * DPAD + lane * 4);
        float m = fmaxf(fmaxf(x.x, x.y), fmaxf(x.z, x.w));
        m = fmaxf(m, __shfl_xor_sync(0xffffffffu, m, 1));
        m = fmaxf(m, __shfl_xor_sync(0xffffffffu, m, 2));
        float4 e;
        e.x = expf(x.x - m); e.y = expf(x.y - m);
        e.z = expf(x.z - m); e.w = expf(x.w - m);
        float s = e.x + e.y + e.z + e.w;
        s += __shfl_xor_sync(0xffffffffu, s, 1);
        s += __shfl_xor_sync(0xffffffffu, s, 2);
        float sc = 0.25f / s;
        e.x *= sc; e.y *= sc; e.z *= sc; e.w *= sc;
        *(float4*)(q + c * DPAD + lane * 4) = e;
    }
}

// softmax over the sequence dim on kT [128][KPAD] — warp per column, all 16 warps
template<int N>
__device__ __forceinline__ void softmax_seq_par(float* __restrict__ kT, int tid)
{
    int lane = tid & 31, wy = tid >> 5;
    for (int col = wy; col < DIM; col += NWARPS) {
        float* p = kT + col * KPAD;
        float v0 = (lane < N) ? p[lane] : -1e30f;
        float v1 = (lane + 32 < N) ? p[lane + 32] : -1e30f;
        float m = fmaxf(v0, v1);
#pragma unroll
        for (int o = 16; o; o >>= 1) m = fmaxf(m, __shfl_xor_sync(0xffffffffu, m, o));
        float e0 = (lane < N) ? expf(v0 - m) : 0.f;
        float e1 = (lane + 32 < N) ? expf(v1 - m) : 0.f;
        float s = e0 + e1;
#pragma unroll
        for (int o = 16; o; o >>= 1) s += __shfl_xor_sync(0xffffffffu, s, o);
        float inv = 1.0f / s;
        if (lane < N)      p[lane]      = e0 * inv;
        if (lane + 32 < N) p[lane + 32] = e1 * inv;
    }
}

// ctx[h][d][e] = sum_c kT[h*16+d][c] * vT[h*16+e][c]
template<int N>
__device__ __forceinline__ void compute_ctx_T(
    const float* __restrict__ kT, const float* __restrict__ vT,
    float* __restrict__ ctx, int tid)
{
    for (int o = tid; o < HEADS * DH * DH; o += NTHREADS) {
        int hh = o >> 8, d = (o >> 4) & 15, e = o & 15;
        const float* kp = kT + (hh * DH + d) * KPAD;
        const float* vp = vT + (hh * DH + e) * KPAD;
        float a = 0.f;
#pragma unroll 4
        for (int c = 0; c < N; c += 2) {
            float2 k2 = *(const float2*)(kp + c);
            float2 v2 = *(const float2*)(vp + c);
            a += k2.x * v2.x + k2.y * v2.y;
        }
        ctx[o] = a;
    }
}

// attn out o[c][col] from Q (stride DPAD) and ctx; write bf16 hi/lo arrays
template<int N>
__device__ __forceinline__ void apply_ctx_split(
    const float* __restrict__ q, const float* __restrict__ ctx,
    __nv_bfloat16* __restrict__ Ahb, __nv_bfloat16* __restrict__ Alb, int tid)
{
    int tx = tid & 31, ty = tid >> 5;
    int hh = tx >> 2;
    int ecol = (tx & 3) * 4;
    for (int c = ty; c < N; c += NWARPS) {
        float4 acc = make_float4(0.f, 0.f, 0.f, 0.f);
        const float* qp = q + c * DPAD + hh * DH;
        const float* cp = ctx + hh * DH * DH + ecol;
#pragma unroll
        for (int d = 0; d < DH; d++) {
            float qv = qp[d];
            float4 cv = *(const float4*)(cp + d * DH);
            acc.x += qv * cv.x; acc.y += qv * cv.y;
            acc.z += qv * cv.z; acc.w += qv * cv.w;
        }
        uint32_t h0, l0, h1, l1;
        split2(acc.x, acc.y, h0, l0);
        split2(acc.z, acc.w, h1, l1);
        int w = hh * 8 + (tx & 3) * 2;
        uint32_t* oh = (uint32_t*)(Ahb + (size_t)c * APAD);
        uint32_t* ol = (uint32_t*)(Alb + (size_t)c * APAD);
        oh[w]     = h0;
        oh[w + 1] = h1;
        ol[w]     = l0;
        ol[w + 1] = l1;
    }
}

// residual epilogue: h += D [+ bias]
template<int N>
__device__ __forceinline__ void epi_add(float* __restrict__ h,
                                        const float* __restrict__ D,
                                        const float* __restrict__ bias,
                                        bool useBias, int tid)
{
    for (int i = tid; i < N * DIM; i += NTHREADS) {
        int c = i >> 7, n = i & 127;
        h[c * DPAD + n] += D[c * DPAD + n] + (useBias ? bias[n] : 0.f);
    }
}

// FF1 epilogue: gelu(D + bias) -> bf16 hi/lo into t arrays at col offset cofs
template<int N>
__device__ __forceinline__ void epi_ff1(const float* __restrict__ D,
                                        __nv_bfloat16* __restrict__ tHi,
                                        __nv_bfloat16* __restrict__ tLo,
                                        const float* __restrict__ bias,
                                        int cofs, int tid)
{
    for (int i = tid; i < N * DIM; i += NTHREADS) {
        int c = i >> 7, n = i & 127;
        float v = gelu_tanh(D[c * DPAD + n] + bias[n]);
        __nv_bfloat16 hv = __float2bfloat16_rn(v);
        __nv_bfloat16 lv = __float2bfloat16_rn(v - __bfloat162float(hv));
        tHi[(size_t)c * TPAD + cofs + n] = hv;
        tLo[(size_t)c * TPAD + cofs + n] = lv;
    }
}

template<int N>
__device__ __forceinline__ void mean_rows(
    const float* __restrict__ h, float* __restrict__ out, int tid)
{
    if (tid < DIM) {
        float s = 0.f;
        for (int c = 0; c < N; c++) s += h[c * DPAD + tid];
        out[tid] = s * (1.0f / N);
    }
}

// ---------------------------------------------------------------------------
// Weight prep: element-wise bf16 hi/lo split into natural [K][128] planes.
// grid = 72 blocks: (stack-layer 0..7) x (weight 0..8).
// ---------------------------------------------------------------------------
__global__ void prep_kernel(StackParams Pc, StackParams Pt)
{
    int blk = blockIdx.x;
    int sl = blk / 9;
    int wi = blk % 9;
    int stack = sl >> 2, l = sl & 3;
    StackParams P = stack ? Pt : Pc;

    const float* src;
    int ldw, colofs, K;
    size_t dstofs = (size_t)sl * 393216;
    if (wi < 4) {
        const float* base = (wi == 0) ? P.Wq : (wi == 1) ? P.Wk : (wi == 2) ? P.Wv : P.Wo;
        src = base + (size_t)l * DIM * DIM;
        ldw = DIM; colofs = 0; K = DIM;
        dstofs += (size_t)wi * 32768;
    } else if (wi < 8) {
        int j = wi - 4;
        src = P.W1 + (size_t)l * DIM * FFD;
        ldw = FFD; colofs = j * DIM; K = DIM;
        dstofs += 131072 + (size_t)j * 32768;
    } else {
        src = P.W2 + (size_t)l * FFD * DIM;
        ldw = DIM; colofs = 0; K = FFD;
        dstofs += 262144;
    }

    __nv_bfloat16* dst = g_wsplit + dstofs;
    int total = K * DIM;
    for (int i = threadIdx.x; i < total; i += blockDim.x) {
        int k = i >> 7, n = i & 127;
        float w = src[(size_t)k * ldw + colofs + n];
        __nv_bfloat16 hv = __float2bfloat16_rn(w);
        __nv_bfloat16 lv = __float2bfloat16_rn(w - __bfloat162float(hv));
        dst[i] = hv;
        dst[total + i] = lv;
    }
}

// ---------------------------------------------------------------------------
// One CTA = one sequence. Full 4-layer stack in SMEM.
// SMEM (floats): h[8448] | D[8448] | Ah,Al (bf16, 8704 floats) |
//                big[17408] (attn: kT,vT [128][68] fp32; ff: tHi,tLo) |
//                wsm[13056] (weight slabs; ctx aliases first 2048 floats mid-attn)
// ---------------------------------------------------------------------------
template<int N, int MODE>
__global__ void __launch_bounds__(NTHREADS, 1)
stack_kernel(const float* __restrict__ xin, float* __restrict__ gout, StackParams P)
{
    extern __shared__ float sm[];
    float*          h   = sm;                                   // 8448
    float*          D   = sm + 8448;                            // 8448
    __nv_bfloat16*  Ah  = (__nv_bfloat16*)(sm + 16896);         // 4352 floats
    __nv_bfloat16*  Al  = Ah + 64 * APAD;                       // 4352 floats
    float*          big = sm + 25600;                           // 17408 floats
    __nv_bfloat16*  wsm = (__nv_bfloat16*)(sm + 43008);         // 13056 floats

    float* kT  = big;                          // 128*68 = 8704 floats
    float* vT  = big + DIM * KPAD;             // 8704
    float* ctx = sm + 43008;                   // aliases wsm (idle mid-attn)
    __nv_bfloat16* tHi = (__nv_bfloat16*)big;  // 64*264 bf16
    __nv_bfloat16* tLo = tHi + 64 * TPAD;

    const int tid = threadIdx.x;
    const __nv_bfloat16* gstack = g_wsplit + (size_t)MODE * 4 * 393216;
    constexpr int LO128 = 128 * 128;
    constexpr int LO512 = 512 * 128;

    // -------- load sequence into h --------
    if (MODE == 0) {
        int sidx = blockIdx.x;
        int b = sidx >> 6, p = sidx & 63;
        const float* xb = xin + (size_t)b * DIM * 62 * 64 + p;
        for (int i = tid; i < N * DIM; i += NTHREADS) {
            int c = i >> 7, e = i & 127;
            h[c * DPAD + e] = xb[(e * 62 + c) * 64];
        }
    } else {
        const float* xb = g_mid + (size_t)blockIdx.x * N * DIM;
        for (int i = tid; i < N * DIM; i += NTHREADS) {
            int c = i >> 7, e = i & 127;
            h[c * DPAD + e] = xb[i];
        }
    }
    __syncthreads();

    for (int l = 0; l < DEPTH; l++) {
        const __nv_bfloat16* gl = gstack + (size_t)l * 393216;
        const float* bo  = P.bo  + l * DIM;
        const float* g1  = P.g1  + l * DIM;
        const float* be1 = P.be1 + l * DIM;
        const float* g2  = P.g2  + l * DIM;
        const float* be2 = P.be2 + l * DIM;
        const float* bf1 = P.bf1 + l * FFD;
        const float* bf2 = P.bf2 + l * DIM;

        // ---- attention ----
        layernorm_split<N>(h, Ah, Al, g1, be1, tid);
        // (no sync: gemm's internal sync orders Ah/Al writes before A reads)

        gemm_qkv(Ah, Al, gl, gl + 32768, gl + 65536, LO128, D, kT, vT, wsm, tid);

        softmax_feat<N>(D, tid);
        softmax_seq_par<N>(kT, tid);
        __syncthreads();                 // kT softmax done before ctx; wsm free for ctx

        compute_ctx_T<N>(kT, vT, ctx, tid);
        __syncthreads();

        apply_ctx_split<N>(D, ctx, Ah, Al, tid);
        __syncthreads();                 // ctx reads done before Wo stages over wsm

        gemm32<4>(Ah, Al, APAD, gl + 98304, LO128, D, wsm, tid);   // Wo
        epi_add<N>(h, D, bo, true, tid);
        __syncthreads();                 // h complete before LN2

        // ---- feed-forward (two 256-wide halves) ----
        layernorm_split<N>(h, Ah, Al, g2, be2, tid);

        for (int half = 0; half < 2; half++) {
#pragma unroll
            for (int j2 = 0; j2 < 2; j2++) {
                int j = half * 2 + j2;
                gemm32<4>(Ah, Al, APAD, gl + 131072 + (size_t)j * 32768, LO128,
                          D, wsm, tid);
                epi_ff1<N>(D, tHi, tLo, bf1 + j * DIM, j2 * DIM, tid);
                // (no sync: next gemm's internal sync covers tHi/tLo and D hazards)
            }
            gemm32<8>(tHi, tLo, TPAD, gl + 262144 + (size_t)half * 32768, LO512,
                      D, wsm, tid);
            epi_add<N>(h, D, bf2, half == 1, tid);
            __syncthreads();
        }
    }

    // -------- mean over tokens --------
    if (MODE == 0) {
        mean_rows<N>(h, g_mid + (size_t)blockIdx.x * DIM, tid);
    } else {
        mean_rows<N>(h, gout + (size_t)blockIdx.x * DIM, tid);
    }
}

// ---------------------------------------------------------------------------
static StackParams mk_params(void* const* d_in, int base)
{
    StackParams p;
    p.Wq  = (const float*)d_in[base + 0];
    p.Wk  = (const float*)d_in[base + 1];
    p.Wv  = (const float*)d_in[base + 2];
    p.Wo  = (const float*)d_in[base + 3];
    p.bo  = (const float*)d_in[base + 4];
    p.g1  = (const float*)d_in[base + 5];
    p.be1 = (const float*)d_in[base + 6];
    p.g2  = (const float*)d_in[base + 7];
    p.be2 = (const float*)d_in[base + 8];
    p.W1  = (const float*)d_in[base + 9];
    p.bf1 = (const float*)d_in[base + 10];
    p.W2  = (const float*)d_in[base + 11];
    p.bf2 = (const float*)d_in[base + 12];
    return p;
}

extern "C" void kernel_launch(void* const* d_in, const int* in_sizes, int n_in,
                              void* d_out, int out_size)
{
    (void)in_sizes; (void)n_in; (void)out_size;

    const float* x = (const float*)d_in[0];
    StackParams Pc = mk_params(d_in, 1);
    StackParams Pt = mk_params(d_in, 14);

    // floats: 8448 + 8448 + 8704 (Ah/Al) + 17408 (big) + 13056 (wsm) = 56064
    const int SMEM = 56064 * (int)sizeof(float);   // 224,256 B

    cudaFuncSetAttribute(stack_kernel<62, 0>,
                         cudaFuncAttributeMaxDynamicSharedMemorySize, SMEM);
    cudaFuncSetAttribute(stack_kernel<64, 1>,
                         cudaFuncAttributeMaxDynamicSharedMemorySize, SMEM);

    // one-time element-wise weight split (no fragment layout assumptions)
    prep_kernel<<<72, NTHREADS>>>(Pc, Pt);

    // channel stack: 4096 sequences of length 62
    stack_kernel<62, 0><<<4096, NTHREADS, SMEM>>>(x, nullptr, Pc);
    // temporal stack: 64 sequences of length 64
    stack_kernel<64, 1><<<64, NTHREADS, SMEM>>>(nullptr, (float*)d_out, Pt);
}